// round 8
// baseline (speedup 1.0000x reference)
#include <cuda_runtime.h>

#define B 8
#define C 512
#define HW 4096
#define TOTAL (B*C*HW)          // 16,777,216
#define TOTAL4 (TOTAL/4)        // 4,194,304
#define GRID 592                // 148 SMs x 4 CTAs (all co-resident, one wave)
#define CHAINB 128              // blocks doing the GEMV chain
#define LOSSB (GRID - CHAINB)   // blocks doing the loss read
#define NW 8

// Scratch (device globals — no allocation allowed)
__device__ float g_text_proj[B*C];
__device__ float g_v_rgb[B*C];
__device__ float g_v_dep[B*C];
__device__ float g_rd[B*2*C];     // per b: [r(512) | d(512)]
__device__ float g_p[B*C];
__device__ float g_fused[B*C];
__device__ double g_acc[2];       // sum((r-d)^2), sum(|r-d|)  (zero-init; reset per replay)
__device__ unsigned int g_count;  // loss finalize counter
__device__ unsigned int g_done;   // whole-kernel completion counter
__device__ unsigned int g_flag;   // fused-ready flag (reset by last-done block)

// Chain-subset barrier: generation counter, monotonic across replays.
__device__ unsigned int g_bar_cnt;
__device__ volatile unsigned int g_bar_gen;

__device__ __forceinline__ void chain_barrier() {
    __syncthreads();
    if (threadIdx.x == 0) {
        __threadfence();
        unsigned int gen = g_bar_gen;
        if (atomicAdd(&g_bar_cnt, 1u) == CHAINB - 1u) {
            g_bar_cnt = 0;
            __threadfence();
            g_bar_gen = gen + 1u;
        } else {
            while (g_bar_gen == gen) __nanosleep(32);
        }
        __threadfence();
    }
    __syncthreads();
}

// Warp computes one output channel for all 8 batches from smem-staged X.
template<int K>
__device__ __forceinline__ void gemv_w(
    const float4* __restrict__ sx4, const float* __restrict__ W,
    const float* __restrict__ bias, float* __restrict__ Y,
    int ldY, int off, int c, int lane)
{
    constexpr int K4 = K / 4;
    const float4* w4 = reinterpret_cast<const float4*>(W) + (size_t)c * K4;
    float acc[B];
#pragma unroll
    for (int b = 0; b < B; ++b) acc[b] = 0.f;
#pragma unroll
    for (int i = 0; i < K4 / 32; ++i) {
        float4 w = w4[i * 32 + lane];
#pragma unroll
        for (int b = 0; b < B; ++b) {
            float4 x = sx4[b * K4 + i * 32 + lane];
            acc[b] += w.x * x.x + w.y * x.y + w.z * x.z + w.w * x.w;
        }
    }
#pragma unroll
    for (int b = 0; b < B; ++b) {
#pragma unroll
        for (int o = 16; o > 0; o >>= 1)
            acc[b] += __shfl_xor_sync(0xffffffffu, acc[b], o);
    }
    if (lane == 0) {
        float bv = bias[c];
#pragma unroll
        for (int b = 0; b < B; ++b) Y[b * ldY + off + c] = acc[b] + bv;
    }
}

__global__ void __launch_bounds__(256, 4) fused_all_kernel(
    const float4* __restrict__ rgb, const float4* __restrict__ dep,
    float4* __restrict__ out, float* __restrict__ out_s,
    const float* __restrict__ text,
    const float* __restrict__ tp_w,   const float* __restrict__ tp_b,
    const float* __restrict__ rgb_wv, const float* __restrict__ rgb_bv,
    const float* __restrict__ dep_wv, const float* __restrict__ dep_bv,
    const float* __restrict__ rgb_wo, const float* __restrict__ rgb_bo,
    const float* __restrict__ dep_wo, const float* __restrict__ dep_bo,
    const float* __restrict__ gate_w, const float* __restrict__ gate_b,
    const float* __restrict__ bn_g,   const float* __restrict__ bn_b)
{
    __shared__ float4 sx4[2048];   // 32KB staged X (chain blocks only use it)
    int tid = threadIdx.x;
    int warp = tid >> 5, lane = tid & 31;

    if (blockIdx.x < CHAINB) {
        // ================= CHAIN ROLE (blocks 0..127) =================
        int gwarp = blockIdx.x * NW + warp;

        // S1: text_proj = text @ tp_w.T + tp_b (512 ch, K=512)
        {
            const float4* X4 = reinterpret_cast<const float4*>(text);
            for (int i = tid; i < 1024; i += 256) sx4[i] = X4[i];
            __syncthreads();
            if (gwarp < 512) gemv_w<512>(sx4, tp_w, tp_b, g_text_proj, 512, 0, gwarp, lane);
        }
        chain_barrier();

        // S2: v = text_proj @ Wv.T + bv (rgb: warps 0-511, dep: 512-1023)
        {
            const float4* X4 = reinterpret_cast<const float4*>(g_text_proj);
            for (int i = tid; i < 1024; i += 256) sx4[i] = X4[i];
            __syncthreads();
            if (gwarp < 512)
                gemv_w<512>(sx4, rgb_wv, rgb_bv, g_v_rgb, 512, 0, gwarp, lane);
            else
                gemv_w<512>(sx4, dep_wv, dep_bv, g_v_dep, 512, 0, gwarp - 512, lane);
        }
        chain_barrier();

        // S3: r = v_rgb @ Wo_r.T + bo ; d = v_dep @ Wo_d.T + bo -> g_rd[b, r|d]
        {
            const float4* Xr = reinterpret_cast<const float4*>(g_v_rgb);
            const float4* Xd = reinterpret_cast<const float4*>(g_v_dep);
            for (int i = tid; i < 1024; i += 256) { sx4[i] = Xr[i]; sx4[1024 + i] = Xd[i]; }
            __syncthreads();
            if (gwarp < 512)
                gemv_w<512>(sx4, rgb_wo, rgb_bo, g_rd, 1024, 0, gwarp, lane);
            else
                gemv_w<512>(sx4 + 1024, dep_wo, dep_bo, g_rd, 1024, 512, gwarp - 512, lane);
        }
        chain_barrier();

        // S4: p = [r|d] @ gate_w.T + gate_b (512 ch, K=1024)
        {
            const float4* X4 = reinterpret_cast<const float4*>(g_rd);
            for (int i = tid; i < 2048; i += 256) sx4[i] = X4[i];
            __syncthreads();
            if (gwarp < 512) gemv_w<1024>(sx4, gate_w, gate_b, g_p, 512, 0, gwarp, lane);
        }
        chain_barrier();

        // S5: block 0 only — BN over batch + sigmoid gate + fuse, then set flag
        if (blockIdx.x == 0) {
#pragma unroll
            for (int cc = 0; cc < 2; ++cc) {
                int c = tid + cc * 256;
                float p[B];
                float mean = 0.f;
#pragma unroll
                for (int b = 0; b < B; ++b) { p[b] = g_p[b*C + c]; mean += p[b]; }
                mean *= (1.f / B);
                float var = 0.f;
#pragma unroll
                for (int b = 0; b < B; ++b) { float d = p[b] - mean; var += d * d; }
                var *= (1.f / B);
                float rstd = rsqrtf(var + 1e-5f);
                float gg = bn_g[c], gb = bn_b[c];
#pragma unroll
                for (int b = 0; b < B; ++b) {
                    float xh   = (p[b] - mean) * rstd;
                    float gate = 1.f / (1.f + expf(-(gg * xh + gb)));
                    float r = g_rd[b*2*C + c];
                    float d = g_rd[b*2*C + C + c];
                    g_fused[b*C + c] = gate * r + (1.f - gate) * d;
                }
            }
            __syncthreads();
            if (tid == 0) {
                __threadfence();
                atomicExch(&g_flag, 1u);   // fused ready
            }
        }
    } else {
        // ================= LOSS ROLE (blocks 128..591): read rgb/dep, reduce =================
        const int NT = LOSSB * 256;
        int t = (blockIdx.x - CHAINB) * 256 + tid;
        float s2 = 0.f, s1 = 0.f;
        for (int i = t; i < TOTAL4; i += 2 * NT) {
            float4 r = rgb[i], d = dep[i];
            int j = i + NT;
            float dx = r.x - d.x, dy = r.y - d.y, dz = r.z - d.z, dw = r.w - d.w;
            if (j < TOTAL4) {
                float4 r2 = rgb[j], d2 = dep[j];
                float ex = r2.x - d2.x, ey = r2.y - d2.y, ez = r2.z - d2.z, ew = r2.w - d2.w;
                s2 += ex*ex + ey*ey + ez*ez + ew*ew;
                s1 += fabsf(ex) + fabsf(ey) + fabsf(ez) + fabsf(ew);
            }
            s2 += dx*dx + dy*dy + dz*dz + dw*dw;
            s1 += fabsf(dx) + fabsf(dy) + fabsf(dz) + fabsf(dw);
        }
#pragma unroll
        for (int o = 16; o > 0; o >>= 1) {
            s2 += __shfl_down_sync(0xffffffffu, s2, o);
            s1 += __shfl_down_sync(0xffffffffu, s1, o);
        }
        __shared__ float sh2[8], sh1[8];
        if ((tid & 31) == 0) { sh2[warp] = s2; sh1[warp] = s1; }
        __syncthreads();
        if (tid == 0) {
            float t2 = 0.f, t1 = 0.f;
#pragma unroll
            for (int j = 0; j < 8; ++j) { t2 += sh2[j]; t1 += sh1[j]; }
            atomicAdd(&g_acc[0], (double)t2);
            atomicAdd(&g_acc[1], (double)t1);
            __threadfence();
            if (atomicAdd(&g_count, 1u) == LOSSB - 1u) {
                g_count = 0;
                const double inv = 1.0 / (double)TOTAL;
                double a0 = atomicAdd(&g_acc[0], 0.0);
                double a1 = atomicAdd(&g_acc[1], 0.0);
                out_s[TOTAL]     = (float)(a0 * inv);   // pixel_loss
                out_s[TOTAL + 1] = (float)(a1 * inv);   // depth_loss
            }
        }
    }

    // ================= WRITE PHASE (all 592 blocks): broadcast fused over HW =================
    if (!(blockIdx.x == 0 && threadIdx.x == 0)) {       // block 0 set the flag itself
        if (tid == 0) {
            while (*((volatile unsigned int*)&g_flag) == 0u) __nanosleep(64);
        }
    }
    __syncthreads();
    __threadfence();

    {
        const int NT = GRID * 256;
        int t = blockIdx.x * 256 + tid;
        for (int i = t; i < TOTAL4; i += NT) {
            float f = g_fused[i >> 10];                 // 1024 float4 per (b,c)
            out[i] = make_float4(f, f, f, f);
        }
    }

    // Completion: last block resets flag + accumulators for the next graph replay.
    __syncthreads();
    if (tid == 0) {
        __threadfence();
        if (atomicAdd(&g_done, 1u) == GRID - 1u) {
            g_done = 0;
            g_flag = 0;
            g_acc[0] = 0.0;
            g_acc[1] = 0.0;
            __threadfence();
        }
    }
}

extern "C" void kernel_launch(void* const* d_in, const int* in_sizes, int n_in,
                              void* d_out, int out_size)
{
    const float* rgb      = (const float*)d_in[0];
    const float* dep      = (const float*)d_in[1];
    const float* text     = (const float*)d_in[2];
    const float* tp_w     = (const float*)d_in[3];
    const float* tp_b     = (const float*)d_in[4];
    const float* rgb_wqkv = (const float*)d_in[5];
    const float* rgb_bqkv = (const float*)d_in[6];
    const float* rgb_wo   = (const float*)d_in[7];
    const float* rgb_bo   = (const float*)d_in[8];
    const float* dep_wqkv = (const float*)d_in[9];
    const float* dep_bqkv = (const float*)d_in[10];
    const float* dep_wo   = (const float*)d_in[11];
    const float* dep_bo   = (const float*)d_in[12];
    const float* gate_w   = (const float*)d_in[13];
    const float* gate_b   = (const float*)d_in[14];
    const float* bn_g     = (const float*)d_in[15];
    const float* bn_b     = (const float*)d_in[16];
    float* out = (float*)d_out;

    fused_all_kernel<<<GRID, 256>>>(
        (const float4*)rgb, (const float4*)dep, (float4*)out, out,
        text, tp_w, tp_b,
        rgb_wqkv + 2*C*C, rgb_bqkv + 2*C,
        dep_wqkv + 2*C*C, dep_bqkv + 2*C,
        rgb_wo, rgb_bo, dep_wo, dep_bo,
        gate_w, gate_b, bn_g, bn_b);
}

// round 9
// speedup vs baseline: 1.2045x; 1.2045x over previous
#include <cuda_runtime.h>

#define B 8
#define C 512
#define HW 4096
#define TOTAL (B*C*HW)          // 16,777,216
#define TOTAL4 (TOTAL/4)        // 4,194,304
#define GRID 740                // 148 SMs x 5 CTAs (all co-resident, one wave)
#define CHAINB 128              // blocks participating in the GEMV chain
#define NW 8
#define NRT 4096                // read tiles  (1024 float4 each, rgb+dep)
#define NWT 4096                // write tiles (1024 float4 each, one (b,c) slab)

// Scratch (device globals — no allocation allowed)
__device__ float g_text_proj[B*C];
__device__ float g_v_rgb[B*C];
__device__ float g_v_dep[B*C];
__device__ float g_rd[B*2*C];     // per b: [r(512) | d(512)]
__device__ float g_p[B*C];
__device__ float g_fused[B*C];
__device__ double g_acc[2];       // sum((r-d)^2), sum(|r-d|)
__device__ unsigned int g_rtile;  // read-tile steal counter
__device__ unsigned int g_wtile;  // write-tile steal counter
__device__ unsigned int g_done;   // completion counter (reset state for replay)
__device__ volatile unsigned int g_flag;   // fused-ready flag

// Chain barrier: generation counter, monotonic across replays.
__device__ unsigned int g_bar_cnt;
__device__ volatile unsigned int g_bar_gen;

__device__ __forceinline__ void chain_bar(unsigned expected, bool wait) {
    __syncthreads();
    if (threadIdx.x == 0) {
        __threadfence();
        unsigned gen = g_bar_gen;
        if (atomicAdd(&g_bar_cnt, 1u) == expected - 1u) {
            g_bar_cnt = 0;
            __threadfence();
            g_bar_gen = gen + 1u;
        } else if (wait) {
            while (g_bar_gen == gen) __nanosleep(32);
        }
        __threadfence();
    }
    __syncthreads();
}

__device__ __forceinline__ void pf_l2(const float* p) {
    asm volatile("prefetch.global.L2 [%0];" :: "l"(p));
}

// Warp computes one output channel (all 8 batches); X staged in smem.
// K4CH float4 per chunk; weight row stride wstride4 float4, chunk offset woff4.
template<int K4CH>
__device__ __forceinline__ void gemv_acc(
    const float4* __restrict__ sx4, const float4* __restrict__ w4row,
    float* acc, int lane)
{
#pragma unroll
    for (int i = 0; i < K4CH / 32; ++i) {
        float4 w = w4row[i * 32 + lane];
#pragma unroll
        for (int b = 0; b < B; ++b) {
            float4 x = sx4[b * K4CH + i * 32 + lane];
            acc[b] += w.x * x.x + w.y * x.y + w.z * x.z + w.w * x.w;
        }
    }
}

__device__ __forceinline__ void warp_reduce_store(
    float* acc, const float* __restrict__ bias, float* __restrict__ Y,
    int ldY, int off, int c, int lane)
{
#pragma unroll
    for (int b = 0; b < B; ++b) {
#pragma unroll
        for (int o = 16; o > 0; o >>= 1)
            acc[b] += __shfl_xor_sync(0xffffffffu, acc[b], o);
    }
    if (lane == 0) {
        float bv = bias[c];
#pragma unroll
        for (int b = 0; b < B; ++b) Y[b * ldY + off + c] = acc[b] + bv;
    }
}

__global__ void __launch_bounds__(256, 5) fused_all_kernel(
    const float4* __restrict__ rgb, const float4* __restrict__ dep,
    float4* __restrict__ out, float* __restrict__ out_s,
    const float* __restrict__ text,
    const float* __restrict__ tp_w,   const float* __restrict__ tp_b,
    const float* __restrict__ rgb_wv, const float* __restrict__ rgb_bv,
    const float* __restrict__ dep_wv, const float* __restrict__ dep_bv,
    const float* __restrict__ rgb_wo, const float* __restrict__ rgb_bo,
    const float* __restrict__ dep_wo, const float* __restrict__ dep_bo,
    const float* __restrict__ gate_w, const float* __restrict__ gate_b,
    const float* __restrict__ bn_g,   const float* __restrict__ bn_b)
{
    __shared__ float4 sx4[1024];    // 16KB staging
    __shared__ unsigned s_tile;
    __shared__ float sh2[8], sh1[8];
    int tid = threadIdx.x;
    int warp = tid >> 5, lane = tid & 31;

    // ====================== CHAIN (blocks 0..127) ======================
    if (blockIdx.x < CHAINB) {
        int gwarp = blockIdx.x * NW + warp;          // 0..1023
        bool lower = (blockIdx.x < 64);              // handles rgb half / S1 / S4

        // L2 prefetch of this warp's later-stage weight rows (hide DRAM latency)
        {
            const float* s2row = (gwarp < 512) ? (rgb_wv + (size_t)gwarp * 512)
                                               : (dep_wv + (size_t)(gwarp - 512) * 512);
            if (lane < 16) pf_l2(s2row + lane * 32);
            const float* s3row = lower ? (rgb_wo + (size_t)gwarp * 512)
                                       : (dep_wo + (size_t)(gwarp - 512) * 512);
            if (lane < 16) pf_l2(s3row + lane * 32);
            if (lower) pf_l2(gate_w + (size_t)gwarp * 1024 + lane * 32);
        }

        // ---- S1: text_proj = text @ tp_w.T + tp_b (512 ch on blocks 0-63) ----
        if (lower) {
            const float4* X4 = reinterpret_cast<const float4*>(text);
            for (int i = tid; i < 1024; i += 256) sx4[i] = X4[i];
            __syncthreads();
            float acc[B] = {0,0,0,0,0,0,0,0};
            gemv_acc<128>(sx4, reinterpret_cast<const float4*>(tp_w) + (size_t)gwarp * 128, acc, lane);
            warp_reduce_store(acc, tp_b, g_text_proj, 512, 0, gwarp, lane);
        }
        chain_bar(CHAINB, true);

        // ---- S2: v = text_proj @ Wv.T + bv (rgb warps 0-511, dep 512-1023) ----
        {
            const float4* X4 = reinterpret_cast<const float4*>(g_text_proj);
            for (int i = tid; i < 1024; i += 256) sx4[i] = X4[i];
            __syncthreads();
            float acc[B] = {0,0,0,0,0,0,0,0};
            if (gwarp < 512) {
                gemv_acc<128>(sx4, reinterpret_cast<const float4*>(rgb_wv) + (size_t)gwarp * 128, acc, lane);
                warp_reduce_store(acc, rgb_bv, g_v_rgb, 512, 0, gwarp, lane);
            } else {
                gemv_acc<128>(sx4, reinterpret_cast<const float4*>(dep_wv) + (size_t)(gwarp - 512) * 128, acc, lane);
                warp_reduce_store(acc, dep_bv, g_v_dep, 512, 0, gwarp - 512, lane);
            }
        }
        chain_bar(CHAINB, true);

        // ---- S3: r/d = v @ Wo.T + bo -> g_rd[b, r|d] ----
        {
            const float4* X4 = reinterpret_cast<const float4*>(lower ? g_v_rgb : g_v_dep);
            for (int i = tid; i < 1024; i += 256) sx4[i] = X4[i];
            __syncthreads();
            float acc[B] = {0,0,0,0,0,0,0,0};
            if (lower) {
                gemv_acc<128>(sx4, reinterpret_cast<const float4*>(rgb_wo) + (size_t)gwarp * 128, acc, lane);
                warp_reduce_store(acc, rgb_bo, g_rd, 1024, 0, gwarp, lane);
            } else {
                gemv_acc<128>(sx4, reinterpret_cast<const float4*>(dep_wo) + (size_t)(gwarp - 512) * 128, acc, lane);
                warp_reduce_store(acc, dep_bo, g_rd, 1024, 512, gwarp - 512, lane);
            }
        }
        // blocks 64-127 arrive and leave for streaming; blocks 0-63 wait
        chain_bar(CHAINB, lower);

        if (lower) {
            // ---- S4: p = [r|d] @ gate_w.T + gate_b (K=1024, two 16KB passes) ----
            float acc[B] = {0,0,0,0,0,0,0,0};
            const float4* rd4 = reinterpret_cast<const float4*>(g_rd);
#pragma unroll
            for (int p = 0; p < 2; ++p) {
                __syncthreads();
                for (int i = tid; i < 1024; i += 256)
                    sx4[i] = rd4[(i >> 7) * 256 + p * 128 + (i & 127)];
                __syncthreads();
                gemv_acc<128>(sx4, reinterpret_cast<const float4*>(gate_w)
                                   + (size_t)gwarp * 256 + p * 128, acc, lane);
            }
            warp_reduce_store(acc, gate_b, g_p, 512, 0, gwarp, lane);
            chain_bar(64, true);

            // ---- S5 (block 0): BN over batch + sigmoid gate + fuse -> flag ----
            if (blockIdx.x == 0) {
#pragma unroll
                for (int cc = 0; cc < 2; ++cc) {
                    int c = tid + cc * 256;
                    float p[B];
                    float mean = 0.f;
#pragma unroll
                    for (int b = 0; b < B; ++b) { p[b] = g_p[b*C + c]; mean += p[b]; }
                    mean *= (1.f / B);
                    float var = 0.f;
#pragma unroll
                    for (int b = 0; b < B; ++b) { float d = p[b] - mean; var += d * d; }
                    var *= (1.f / B);
                    float rstd = rsqrtf(var + 1e-5f);
                    float gg = bn_g[c], gb = bn_b[c];
#pragma unroll
                    for (int b = 0; b < B; ++b) {
                        float xh   = (p[b] - mean) * rstd;
                        float gate = 1.f / (1.f + expf(-(gg * xh + gb)));
                        float r = g_rd[b*2*C + c];
                        float d = g_rd[b*2*C + C + c];
                        g_fused[b*C + c] = gate * r + (1.f - gate) * d;
                    }
                }
                __syncthreads();
                if (tid == 0) {
                    __threadfence();
                    g_flag = 1u;
                }
            }
        }
    }

    // ====================== PHASE A: steal read tiles, reduce losses ======================
    float s2 = 0.f, s1 = 0.f;
    for (;;) {
        if (tid == 0) s_tile = atomicAdd(&g_rtile, 1u);
        __syncthreads();
        unsigned t = s_tile;
        __syncthreads();
        if (t >= NRT) break;
        int base = t * 1024 + tid;
#pragma unroll
        for (int j = 0; j < 4; ++j) {
            float4 r = rgb[base + j * 256];
            float4 d = dep[base + j * 256];
            float dx = r.x - d.x, dy = r.y - d.y, dz = r.z - d.z, dw = r.w - d.w;
            s2 += dx*dx + dy*dy + dz*dz + dw*dw;
            s1 += fabsf(dx) + fabsf(dy) + fabsf(dz) + fabsf(dw);
        }
    }
#pragma unroll
    for (int o = 16; o > 0; o >>= 1) {
        s2 += __shfl_down_sync(0xffffffffu, s2, o);
        s1 += __shfl_down_sync(0xffffffffu, s1, o);
    }
    if (lane == 0) { sh2[warp] = s2; sh1[warp] = s1; }
    __syncthreads();
    if (tid == 0) {
        float t2 = 0.f, t1 = 0.f;
#pragma unroll
        for (int j = 0; j < 8; ++j) { t2 += sh2[j]; t1 += sh1[j]; }
        atomicAdd(&g_acc[0], (double)t2);
        atomicAdd(&g_acc[1], (double)t1);
    }

    // ====================== PHASE B: wait fused, steal write tiles ======================
    if (tid == 0) {
        while (g_flag == 0u) __nanosleep(64);
    }
    __syncthreads();
    __threadfence();

    for (;;) {
        if (tid == 0) s_tile = atomicAdd(&g_wtile, 1u);
        __syncthreads();
        unsigned t = s_tile;
        __syncthreads();
        if (t >= NWT) break;
        float f = g_fused[t];
        float4 fv = make_float4(f, f, f, f);
        int base = t * 1024 + tid;
#pragma unroll
        for (int j = 0; j < 4; ++j) out[base + j * 256] = fv;
    }

    // ====================== Completion: last block finalizes + resets ======================
    __syncthreads();
    if (tid == 0) {
        __threadfence();
        if (atomicAdd(&g_done, 1u) == GRID - 1u) {
            const double inv = 1.0 / (double)TOTAL;
            double a0 = g_acc[0], a1 = g_acc[1];
            out_s[TOTAL]     = (float)(a0 * inv);   // pixel_loss
            out_s[TOTAL + 1] = (float)(a1 * inv);   // depth_loss
            // reset for next graph replay
            g_acc[0] = 0.0; g_acc[1] = 0.0;
            g_rtile = 0u; g_wtile = 0u; g_flag = 0u; g_done = 0u;
            __threadfence();
        }
    }
}

extern "C" void kernel_launch(void* const* d_in, const int* in_sizes, int n_in,
                              void* d_out, int out_size)
{
    const float* rgb      = (const float*)d_in[0];
    const float* dep      = (const float*)d_in[1];
    const float* text     = (const float*)d_in[2];
    const float* tp_w     = (const float*)d_in[3];
    const float* tp_b     = (const float*)d_in[4];
    const float* rgb_wqkv = (const float*)d_in[5];
    const float* rgb_bqkv = (const float*)d_in[6];
    const float* rgb_wo   = (const float*)d_in[7];
    const float* rgb_bo   = (const float*)d_in[8];
    const float* dep_wqkv = (const float*)d_in[9];
    const float* dep_bqkv = (const float*)d_in[10];
    const float* dep_wo   = (const float*)d_in[11];
    const float* dep_bo   = (const float*)d_in[12];
    const float* gate_w   = (const float*)d_in[13];
    const float* gate_b   = (const float*)d_in[14];
    const float* bn_g     = (const float*)d_in[15];
    const float* bn_b     = (const float*)d_in[16];
    float* out = (float*)d_out;

    fused_all_kernel<<<GRID, 256>>>(
        (const float4*)rgb, (const float4*)dep, (float4*)out, out,
        text, tp_w, tp_b,
        rgb_wqkv + 2*C*C, rgb_bqkv + 2*C,
        dep_wqkv + 2*C*C, dep_bqkv + 2*C,
        rgb_wo, rgb_bo, dep_wo, dep_bo,
        gate_w, gate_b, bn_g, bn_b);
}

// round 10
// speedup vs baseline: 1.4343x; 1.1908x over previous
#include <cuda_runtime.h>

#define B 8
#define C 512
#define HW 4096
#define TOTAL (B*C*HW)          // 16,777,216
#define TOTAL4 (TOTAL/4)        // 4,194,304
#define CG 64                   // chain grid (64 CTAs x 512 thr = 1024 warps)
#define CT 512
#define NWARP 16
#define LGRID 1184              // fuse_loss grid: 148 SMs x 8 CTAs

// Scratch (device globals — no allocation allowed)
__device__ float g_text_proj[B*C];
__device__ float g_v_rgb[B*C];
__device__ float g_v_dep[B*C];
__device__ float g_rd[B*2*C];     // per b: [r(512) | d(512)]
__device__ float g_fused[B*C];
__device__ double g_acc[2];       // sum((r-d)^2), sum(|r-d|)
__device__ unsigned int g_count;  // fuse_loss finalize counter

// Chain barrier: generation counter, monotonic across graph replays.
__device__ unsigned int g_bar_cnt;
__device__ volatile unsigned int g_bar_gen;

__device__ __forceinline__ void chain_bar() {
    __syncthreads();
    if (threadIdx.x == 0) {
        __threadfence();
        unsigned gen = g_bar_gen;
        if (atomicAdd(&g_bar_cnt, 1u) == CG - 1u) {
            g_bar_cnt = 0;
            __threadfence();
            g_bar_gen = gen + 1u;
        } else {
            while (g_bar_gen == gen) __nanosleep(32);
        }
        __threadfence();
    }
    __syncthreads();
}

__device__ __forceinline__ void pf_l2(const float* p) {
    asm volatile("prefetch.global.L2 [%0];" :: "l"(p));
}

// Warp-level GEMV accumulate: K4 float4 of smem X per batch, weight row w4row.
template<int K4>
__device__ __forceinline__ void gemv_acc(
    const float4* __restrict__ sx4, const float4* __restrict__ w4row,
    float* acc, int lane)
{
#pragma unroll
    for (int i = 0; i < K4 / 32; ++i) {
        float4 w = w4row[i * 32 + lane];
#pragma unroll
        for (int b = 0; b < B; ++b) {
            float4 x = sx4[b * K4 + i * 32 + lane];
            acc[b] += w.x * x.x + w.y * x.y + w.z * x.z + w.w * x.w;
        }
    }
}

// xor-reduce: afterwards EVERY lane holds the full sums for all 8 batches.
__device__ __forceinline__ void warp_allreduce(float* acc) {
#pragma unroll
    for (int b = 0; b < B; ++b) {
#pragma unroll
        for (int o = 16; o > 0; o >>= 1)
            acc[b] += __shfl_xor_sync(0xffffffffu, acc[b], o);
    }
}

// GEMV chain + BN/gate/fuse: 64 CTAs x 512 threads, 3 grid barriers.
__global__ void __launch_bounds__(CT) chain_kernel(
    const float* __restrict__ text,
    const float* __restrict__ tp_w,   const float* __restrict__ tp_b,
    const float* __restrict__ rgb_wv, const float* __restrict__ rgb_bv,
    const float* __restrict__ dep_wv, const float* __restrict__ dep_bv,
    const float* __restrict__ rgb_wo, const float* __restrict__ rgb_bo,
    const float* __restrict__ dep_wo, const float* __restrict__ dep_bo,
    const float* __restrict__ gate_w, const float* __restrict__ gate_b,
    const float* __restrict__ bn_g,   const float* __restrict__ bn_b)
{
    __shared__ float4 sx4[2048];   // 32KB staging (S4 needs full 8x1024)
    int tid = threadIdx.x;
    int warp = tid >> 5, lane = tid & 31;
    int gwarp = blockIdx.x * NWARP + warp;     // 0..1023
    bool lower = (gwarp < 512);

    if (blockIdx.x == 0 && tid == 0) { g_acc[0] = 0.0; g_acc[1] = 0.0; }

    // ---- L2 prefetch of this warp's stage-2/3/4 weight rows (hides DRAM for S2+) ----
    {
        const float* s2row = lower ? (rgb_wv + (size_t)gwarp * 512)
                                   : (dep_wv + (size_t)(gwarp - 512) * 512);
        if (lane < 16) pf_l2(s2row + lane * 32);
        const float* s3row = lower ? (rgb_wo + (size_t)gwarp * 512)
                                   : (dep_wo + (size_t)(gwarp - 512) * 512);
        if (lane < 16) pf_l2(s3row + lane * 32);
        if (lower) pf_l2(gate_w + (size_t)gwarp * 1024 + lane * 32);  // 4KB row
    }

    // ---- S1: text_proj = text @ tp_w.T + tp_b  (512 ch on blocks 0..31) ----
    if (lower) {
        const float4* X4 = reinterpret_cast<const float4*>(text);
        for (int i = tid; i < 1024; i += CT) sx4[i] = X4[i];
        __syncthreads();
        float acc[B] = {0,0,0,0,0,0,0,0};
        gemv_acc<128>(sx4, reinterpret_cast<const float4*>(tp_w) + (size_t)gwarp * 128, acc, lane);
        warp_allreduce(acc);
        if (lane == 0) {
            float bv = tp_b[gwarp];
#pragma unroll
            for (int b = 0; b < B; ++b) g_text_proj[b * C + gwarp] = acc[b] + bv;
        }
    }
    chain_bar();

    // ---- S2: v = text_proj @ Wv.T + bv  (rgb: gwarp 0-511, dep: 512-1023) ----
    {
        const float4* X4 = reinterpret_cast<const float4*>(g_text_proj);
        for (int i = tid; i < 1024; i += CT) sx4[i] = X4[i];
        __syncthreads();
        float acc[B] = {0,0,0,0,0,0,0,0};
        if (lower) {
            gemv_acc<128>(sx4, reinterpret_cast<const float4*>(rgb_wv) + (size_t)gwarp * 128, acc, lane);
            warp_allreduce(acc);
            if (lane == 0) {
                float bv = rgb_bv[gwarp];
#pragma unroll
                for (int b = 0; b < B; ++b) g_v_rgb[b * C + gwarp] = acc[b] + bv;
            }
        } else {
            int c = gwarp - 512;
            gemv_acc<128>(sx4, reinterpret_cast<const float4*>(dep_wv) + (size_t)c * 128, acc, lane);
            warp_allreduce(acc);
            if (lane == 0) {
                float bv = dep_bv[c];
#pragma unroll
                for (int b = 0; b < B; ++b) g_v_dep[b * C + c] = acc[b] + bv;
            }
        }
    }
    chain_bar();

    // ---- S3: r = v_rgb @ Wo_r.T + bo_r ; d = v_dep @ Wo_d.T + bo_d -> g_rd[b, r|d] ----
    {
        const float4* X4 = reinterpret_cast<const float4*>(lower ? g_v_rgb : g_v_dep);
        for (int i = tid; i < 1024; i += CT) sx4[i] = X4[i];
        __syncthreads();
        float acc[B] = {0,0,0,0,0,0,0,0};
        if (lower) {
            gemv_acc<128>(sx4, reinterpret_cast<const float4*>(rgb_wo) + (size_t)gwarp * 128, acc, lane);
            warp_allreduce(acc);
            if (lane == 0) {
                float bv = rgb_bo[gwarp];
#pragma unroll
                for (int b = 0; b < B; ++b) g_rd[b * 2 * C + gwarp] = acc[b] + bv;
            }
        } else {
            int c = gwarp - 512;
            gemv_acc<128>(sx4, reinterpret_cast<const float4*>(dep_wo) + (size_t)c * 128, acc, lane);
            warp_allreduce(acc);
            if (lane == 0) {
                float bv = dep_bo[c];
#pragma unroll
                for (int b = 0; b < B; ++b) g_rd[b * 2 * C + C + c] = acc[b] + bv;
            }
        }
    }
    chain_bar();

    // ---- S4 + S5 fused: p = [r|d] @ gate_w.T + gate_b, then BN over batch +
    //      sigmoid gate + fuse — all inside the owning warp (no more barriers). ----
    if (lower) {
        const float4* X4 = reinterpret_cast<const float4*>(g_rd);
        for (int i = tid; i < 2048; i += CT) sx4[i] = X4[i];
        __syncthreads();
        float acc[B] = {0,0,0,0,0,0,0,0};
        gemv_acc<256>(sx4, reinterpret_cast<const float4*>(gate_w) + (size_t)gwarp * 256, acc, lane);
        warp_allreduce(acc);        // every lane now has all 8 batch sums

        int c = gwarp;
        float gbias = gate_b[c];
        float p[B];
        float mean = 0.f;
#pragma unroll
        for (int b = 0; b < B; ++b) { p[b] = acc[b] + gbias; mean += p[b]; }
        mean *= (1.f / B);
        float var = 0.f;
#pragma unroll
        for (int b = 0; b < B; ++b) { float d = p[b] - mean; var += d * d; }
        var *= (1.f / B);
        float rstd = rsqrtf(var + 1e-5f);
        float gg = bn_g[c], gb = bn_b[c];
        if (lane < B) {
            int b = lane;
            float xh   = (p[b] - mean) * rstd;
            float gate = 1.f / (1.f + expf(-(gg * xh + gb)));
            float r = g_rd[b * 2 * C + c];
            float d = g_rd[b * 2 * C + C + c];
            g_fused[b * C + c] = gate * r + (1.f - gate) * d;
        }
    }
}

// Broadcast fused over HW + both loss reductions in one HBM pass.
// Streaming loads/stores (.cs) keep dead data out of L2.
__global__ void __launch_bounds__(256) fuse_loss_kernel(
    const float4* __restrict__ rgb, const float4* __restrict__ dep,
    float4* __restrict__ out, float* __restrict__ out_s)
{
    float s2 = 0.f, s1 = 0.f;
    int stride = gridDim.x * blockDim.x;
    for (int i = blockIdx.x * blockDim.x + threadIdx.x; i < TOTAL4; i += stride) {
        int bc  = i >> 10;              // 1024 float4 per (b,c)
        float f = g_fused[bc];
        float4 r = __ldcs(rgb + i);
        float4 d = __ldcs(dep + i);
        float dx = r.x - d.x, dy = r.y - d.y, dz = r.z - d.z, dw = r.w - d.w;
        s2 += dx*dx + dy*dy + dz*dz + dw*dw;
        s1 += fabsf(dx) + fabsf(dy) + fabsf(dz) + fabsf(dw);
        __stcs(out + i, make_float4(f, f, f, f));
    }
#pragma unroll
    for (int o = 16; o > 0; o >>= 1) {
        s2 += __shfl_down_sync(0xffffffffu, s2, o);
        s1 += __shfl_down_sync(0xffffffffu, s1, o);
    }
    __shared__ float sh2[8], sh1[8];
    int w = threadIdx.x >> 5, l = threadIdx.x & 31;
    if (l == 0) { sh2[w] = s2; sh1[w] = s1; }
    __syncthreads();
    if (threadIdx.x == 0) {
        float t2 = 0.f, t1 = 0.f;
#pragma unroll
        for (int j = 0; j < 8; ++j) { t2 += sh2[j]; t1 += sh1[j]; }
        atomicAdd(&g_acc[0], (double)t2);
        atomicAdd(&g_acc[1], (double)t1);
        __threadfence();
        if (atomicAdd(&g_count, 1u) == gridDim.x - 1u) {
            g_count = 0;                       // reset for next replay
            const double inv = 1.0 / (double)TOTAL;
            double a0 = atomicAdd(&g_acc[0], 0.0);
            double a1 = atomicAdd(&g_acc[1], 0.0);
            out_s[TOTAL]     = (float)(a0 * inv);   // pixel_loss
            out_s[TOTAL + 1] = (float)(a1 * inv);   // depth_loss
        }
    }
}

extern "C" void kernel_launch(void* const* d_in, const int* in_sizes, int n_in,
                              void* d_out, int out_size)
{
    const float* rgb      = (const float*)d_in[0];
    const float* dep      = (const float*)d_in[1];
    const float* text     = (const float*)d_in[2];
    const float* tp_w     = (const float*)d_in[3];
    const float* tp_b     = (const float*)d_in[4];
    const float* rgb_wqkv = (const float*)d_in[5];
    const float* rgb_bqkv = (const float*)d_in[6];
    const float* rgb_wo   = (const float*)d_in[7];
    const float* rgb_bo   = (const float*)d_in[8];
    const float* dep_wqkv = (const float*)d_in[9];
    const float* dep_bqkv = (const float*)d_in[10];
    const float* dep_wo   = (const float*)d_in[11];
    const float* dep_bo   = (const float*)d_in[12];
    const float* gate_w   = (const float*)d_in[13];
    const float* gate_b   = (const float*)d_in[14];
    const float* bn_g     = (const float*)d_in[15];
    const float* bn_b     = (const float*)d_in[16];
    float* out = (float*)d_out;

    chain_kernel<<<CG, CT>>>(
        text, tp_w, tp_b,
        rgb_wqkv + 2*C*C, rgb_bqkv + 2*C,
        dep_wqkv + 2*C*C, dep_bqkv + 2*C,
        rgb_wo, rgb_bo, dep_wo, dep_bo,
        gate_w, gate_b, bn_g, bn_b);

    fuse_loss_kernel<<<LGRID, 256>>>(
        (const float4*)rgb, (const float4*)dep, (float4*)out, out);
}

// round 11
// speedup vs baseline: 1.5406x; 1.0741x over previous
#include <cuda_runtime.h>

#define B 8
#define C 512
#define HW 4096
#define TOTAL (B*C*HW)          // 16,777,216
#define TOTAL4 (TOTAL/4)        // 4,194,304
#define CG 64                   // chain grid (64 CTAs x 512 thr = 1024 warps)
#define CT 512
#define NWARP 16
#define LGRID 1184              // fuse_loss grid: 148 SMs x 8 CTAs

// Scratch (device globals — no allocation allowed)
__device__ float g_text_proj[B*C];
__device__ float g_v_rgb[B*C];
__device__ float g_v_dep[B*C];
__device__ float g_rd[B*2*C];     // per b: [r(512) | d(512)]
__device__ float g_fused[B*C];
__device__ double g_acc[2];       // zero-init; finalize resets after use (replay-safe)
__device__ unsigned int g_count;  // loss finalize counter

// Chain barrier: generation counter, monotonic across graph replays.
__device__ unsigned int g_bar_cnt;
__device__ volatile unsigned int g_bar_gen;

__device__ __forceinline__ void chain_bar() {
    __syncthreads();
    if (threadIdx.x == 0) {
        __threadfence();
        unsigned gen = g_bar_gen;
        if (atomicAdd(&g_bar_cnt, 1u) == CG - 1u) {
            g_bar_cnt = 0;
            __threadfence();
            g_bar_gen = gen + 1u;
        } else {
            while (g_bar_gen == gen) __nanosleep(32);
        }
        __threadfence();
    }
    __syncthreads();
}

__device__ __forceinline__ void pf_l2(const float* p) {
    asm volatile("prefetch.global.L2 [%0];" :: "l"(p));
}

template<int K4>
__device__ __forceinline__ void gemv_acc(
    const float4* __restrict__ sx4, const float4* __restrict__ w4row,
    float* acc, int lane)
{
#pragma unroll
    for (int i = 0; i < K4 / 32; ++i) {
        float4 w = w4row[i * 32 + lane];
#pragma unroll
        for (int b = 0; b < B; ++b) {
            float4 x = sx4[b * K4 + i * 32 + lane];
            acc[b] += w.x * x.x + w.y * x.y + w.z * x.z + w.w * x.w;
        }
    }
}

// xor-reduce: afterwards EVERY lane holds the full sums for all 8 batches.
__device__ __forceinline__ void warp_allreduce(float* acc) {
#pragma unroll
    for (int b = 0; b < B; ++b) {
#pragma unroll
        for (int o = 16; o > 0; o >>= 1)
            acc[b] += __shfl_xor_sync(0xffffffffu, acc[b], o);
    }
}

// GEMV chain + BN/gate/fuse: 64 CTAs x 512 threads, 3 grid barriers.
__global__ void __launch_bounds__(CT) chain_kernel(
    const float* __restrict__ text,
    const float* __restrict__ tp_w,   const float* __restrict__ tp_b,
    const float* __restrict__ rgb_wv, const float* __restrict__ rgb_bv,
    const float* __restrict__ dep_wv, const float* __restrict__ dep_bv,
    const float* __restrict__ rgb_wo, const float* __restrict__ rgb_bo,
    const float* __restrict__ dep_wo, const float* __restrict__ dep_bo,
    const float* __restrict__ gate_w, const float* __restrict__ gate_b,
    const float* __restrict__ bn_g,   const float* __restrict__ bn_b)
{
#if __CUDA_ARCH__ >= 900
    if (threadIdx.x == 0) cudaTriggerProgrammaticLaunchCompletion();
#endif
    __shared__ float4 sx4[2048];   // 32KB staging (S4 needs full 8x1024)
    int tid = threadIdx.x;
    int warp = tid >> 5, lane = tid & 31;
    int gwarp = blockIdx.x * NWARP + warp;     // 0..1023
    bool lower = (gwarp < 512);

    // ---- L2 prefetch of this warp's stage-2/3/4 weight rows ----
    {
        const float* s2row = lower ? (rgb_wv + (size_t)gwarp * 512)
                                   : (dep_wv + (size_t)(gwarp - 512) * 512);
        if (lane < 16) pf_l2(s2row + lane * 32);
        const float* s3row = lower ? (rgb_wo + (size_t)gwarp * 512)
                                   : (dep_wo + (size_t)(gwarp - 512) * 512);
        if (lane < 16) pf_l2(s3row + lane * 32);
        if (lower) pf_l2(gate_w + (size_t)gwarp * 1024 + lane * 32);
    }

    // ---- S1: text_proj = text @ tp_w.T + tp_b ----
    if (lower) {
        const float4* X4 = reinterpret_cast<const float4*>(text);
        for (int i = tid; i < 1024; i += CT) sx4[i] = X4[i];
        __syncthreads();
        float acc[B] = {0,0,0,0,0,0,0,0};
        gemv_acc<128>(sx4, reinterpret_cast<const float4*>(tp_w) + (size_t)gwarp * 128, acc, lane);
        warp_allreduce(acc);
        if (lane == 0) {
            float bv = tp_b[gwarp];
#pragma unroll
            for (int b = 0; b < B; ++b) g_text_proj[b * C + gwarp] = acc[b] + bv;
        }
    }
    chain_bar();

    // ---- S2: v = text_proj @ Wv.T + bv ----
    {
        const float4* X4 = reinterpret_cast<const float4*>(g_text_proj);
        for (int i = tid; i < 1024; i += CT) sx4[i] = X4[i];
        __syncthreads();
        float acc[B] = {0,0,0,0,0,0,0,0};
        if (lower) {
            gemv_acc<128>(sx4, reinterpret_cast<const float4*>(rgb_wv) + (size_t)gwarp * 128, acc, lane);
            warp_allreduce(acc);
            if (lane == 0) {
                float bv = rgb_bv[gwarp];
#pragma unroll
                for (int b = 0; b < B; ++b) g_v_rgb[b * C + gwarp] = acc[b] + bv;
            }
        } else {
            int c = gwarp - 512;
            gemv_acc<128>(sx4, reinterpret_cast<const float4*>(dep_wv) + (size_t)c * 128, acc, lane);
            warp_allreduce(acc);
            if (lane == 0) {
                float bv = dep_bv[c];
#pragma unroll
                for (int b = 0; b < B; ++b) g_v_dep[b * C + c] = acc[b] + bv;
            }
        }
    }
    chain_bar();

    // ---- S3: r/d = v @ Wo.T + bo -> g_rd[b, r|d] ----
    {
        const float4* X4 = reinterpret_cast<const float4*>(lower ? g_v_rgb : g_v_dep);
        for (int i = tid; i < 1024; i += CT) sx4[i] = X4[i];
        __syncthreads();
        float acc[B] = {0,0,0,0,0,0,0,0};
        if (lower) {
            gemv_acc<128>(sx4, reinterpret_cast<const float4*>(rgb_wo) + (size_t)gwarp * 128, acc, lane);
            warp_allreduce(acc);
            if (lane == 0) {
                float bv = rgb_bo[gwarp];
#pragma unroll
                for (int b = 0; b < B; ++b) g_rd[b * 2 * C + gwarp] = acc[b] + bv;
            }
        } else {
            int c = gwarp - 512;
            gemv_acc<128>(sx4, reinterpret_cast<const float4*>(dep_wo) + (size_t)c * 128, acc, lane);
            warp_allreduce(acc);
            if (lane == 0) {
                float bv = dep_bo[c];
#pragma unroll
                for (int b = 0; b < B; ++b) g_rd[b * 2 * C + C + c] = acc[b] + bv;
            }
        }
    }
    chain_bar();

    // ---- S4 + S5 fused: gate GEMV (K=1024) + BN over batch + sigmoid + fuse ----
    if (lower) {
        const float4* X4 = reinterpret_cast<const float4*>(g_rd);
        for (int i = tid; i < 2048; i += CT) sx4[i] = X4[i];
        __syncthreads();
        float acc[B] = {0,0,0,0,0,0,0,0};
        gemv_acc<256>(sx4, reinterpret_cast<const float4*>(gate_w) + (size_t)gwarp * 256, acc, lane);
        warp_allreduce(acc);        // every lane now has all 8 batch sums

        int c = gwarp;
        float gbias = gate_b[c];
        float p[B];
        float mean = 0.f;
#pragma unroll
        for (int b = 0; b < B; ++b) { p[b] = acc[b] + gbias; mean += p[b]; }
        mean *= (1.f / B);
        float var = 0.f;
#pragma unroll
        for (int b = 0; b < B; ++b) { float d = p[b] - mean; var += d * d; }
        var *= (1.f / B);
        float rstd = rsqrtf(var + 1e-5f);
        float gg = bn_g[c], gb = bn_b[c];
        if (lane < B) {
            int b = lane;
            float xh   = (p[b] - mean) * rstd;
            float gate = 1.f / (1.f + expf(-(gg * xh + gb)));
            float r = g_rd[b * 2 * C + c];
            float d = g_rd[b * 2 * C + C + c];
            g_fused[b * C + c] = gate * r + (1.f - gate) * d;
        }
    }
}

// PDL secondary: phase A = loss read+reduce (independent of chain, overlaps it),
// then grid-dependency sync, then phase B = broadcast write of g_fused.
__global__ void __launch_bounds__(256) fuse_loss_kernel(
    const float4* __restrict__ rgb, const float4* __restrict__ dep,
    float4* __restrict__ out, float* __restrict__ out_s)
{
    int tid = threadIdx.x;
    int stride = gridDim.x * blockDim.x;
    int t0 = blockIdx.x * blockDim.x + tid;

    // ---- Phase A: read 128MB, reduce both losses ----
    float s2 = 0.f, s1 = 0.f;
    for (int i = t0; i < TOTAL4; i += stride) {
        float4 r = __ldcs(rgb + i);
        float4 d = __ldcs(dep + i);
        float dx = r.x - d.x, dy = r.y - d.y, dz = r.z - d.z, dw = r.w - d.w;
        s2 += dx*dx + dy*dy + dz*dz + dw*dw;
        s1 += fabsf(dx) + fabsf(dy) + fabsf(dz) + fabsf(dw);
    }
#pragma unroll
    for (int o = 16; o > 0; o >>= 1) {
        s2 += __shfl_down_sync(0xffffffffu, s2, o);
        s1 += __shfl_down_sync(0xffffffffu, s1, o);
    }
    __shared__ float sh2[8], sh1[8];
    int w = tid >> 5, l = tid & 31;
    if (l == 0) { sh2[w] = s2; sh1[w] = s1; }
    __syncthreads();
    if (tid == 0) {
        float t2 = 0.f, t1 = 0.f;
#pragma unroll
        for (int j = 0; j < 8; ++j) { t2 += sh2[j]; t1 += sh1[j]; }
        atomicAdd(&g_acc[0], (double)t2);
        atomicAdd(&g_acc[1], (double)t1);
        __threadfence();
        if (atomicAdd(&g_count, 1u) == gridDim.x - 1u) {
            g_count = 0;
            const double inv = 1.0 / (double)TOTAL;
            double a0 = atomicAdd(&g_acc[0], 0.0);
            double a1 = atomicAdd(&g_acc[1], 0.0);
            out_s[TOTAL]     = (float)(a0 * inv);   // pixel_loss
            out_s[TOTAL + 1] = (float)(a1 * inv);   // depth_loss
            g_acc[0] = 0.0; g_acc[1] = 0.0;          // reset for next replay
            __threadfence();
        }
    }

    // ---- Wait for chain completion (memory made visible) ----
#if __CUDA_ARCH__ >= 900
    cudaGridDependencySynchronize();
#endif

    // ---- Phase B: broadcast fused over HW (64MB write) ----
    for (int i = t0; i < TOTAL4; i += stride) {
        float f = g_fused[i >> 10];                 // 1024 float4 per (b,c)
        __stcs(out + i, make_float4(f, f, f, f));
    }
}

extern "C" void kernel_launch(void* const* d_in, const int* in_sizes, int n_in,
                              void* d_out, int out_size)
{
    const float* rgb      = (const float*)d_in[0];
    const float* dep      = (const float*)d_in[1];
    const float* text     = (const float*)d_in[2];
    const float* tp_w     = (const float*)d_in[3];
    const float* tp_b     = (const float*)d_in[4];
    const float* rgb_wqkv = (const float*)d_in[5];
    const float* rgb_bqkv = (const float*)d_in[6];
    const float* rgb_wo   = (const float*)d_in[7];
    const float* rgb_bo   = (const float*)d_in[8];
    const float* dep_wqkv = (const float*)d_in[9];
    const float* dep_bqkv = (const float*)d_in[10];
    const float* dep_wo   = (const float*)d_in[11];
    const float* dep_bo   = (const float*)d_in[12];
    const float* gate_w   = (const float*)d_in[13];
    const float* gate_b   = (const float*)d_in[14];
    const float* bn_g     = (const float*)d_in[15];
    const float* bn_b     = (const float*)d_in[16];
    float* out = (float*)d_out;

    chain_kernel<<<CG, CT>>>(
        text, tp_w, tp_b,
        rgb_wqkv + 2*C*C, rgb_bqkv + 2*C,
        dep_wqkv + 2*C*C, dep_bqkv + 2*C,
        rgb_wo, rgb_bo, dep_wo, dep_bo,
        gate_w, gate_b, bn_g, bn_b);

    // PDL secondary: may start while chain runs; phase B gated by
    // cudaGridDependencySynchronize() inside the kernel.
    cudaLaunchConfig_t cfg = {};
    cfg.gridDim  = dim3(LGRID);
    cfg.blockDim = dim3(256);
    cfg.dynamicSmemBytes = 0;
    cfg.stream = 0;
    cudaLaunchAttribute attr[1];
    attr[0].id = cudaLaunchAttributeProgrammaticStreamSerialization;
    attr[0].val.programmaticStreamSerializationAllowed = 1;
    cfg.attrs = attr;
    cfg.numAttrs = 1;
    cudaLaunchKernelEx(&cfg, fuse_loss_kernel,
                       (const float4*)rgb, (const float4*)dep, (float4*)out, out);
}